// round 8
// baseline (speedup 1.0000x reference)
#include <cuda_runtime.h>
#include <cstdint>

#define N_ENTITIES 100000
#define N_USERS    50000
#define N_FACTORS  4
#define N_RELATIONS 32
#define N_REL_USED 31
#define N_META     8
#define CHANNEL    64
#define N_EDGES    1600000
#define NNZ_CNT    1000000

// persistent-grid split for the fused scatter
#define EDGE_BLOCKS 740
#define SPMM_BLOCKS 444
#define TOTAL_BLOCKS (EDGE_BLOCKS + SPMM_BLOCKS)
#define HW_PER_BLOCK 16                     // 256 threads / 16 lanes

// prep kernel split
#define ZERO_BLOCKS 296
#define ATT_BLOCKS  888
#define PREP_BLOCKS (ZERO_BLOCKS + ATT_BLOCKS + 1)   // +1 block for disen

// final kernel split
#define ENTF_BLOCKS 6250     // entity mean: 1.6M float4 / 256
#define USERF_BLOCKS 6250    // users: 50000 / 8 warps
#define FINAL_BLOCKS (ENTF_BLOCKS + USERF_BLOCKS)

// ------------------------- device-global scratch ---------------------------
__device__ float g_cnt[N_ENTITIES];
__device__ float g_disen[N_FACTORS * CHANNEL];
__device__ float g_att[N_ENTITIES * N_REL_USED];   // sigmoid(ent[h] . rel[r])

__device__ __forceinline__ void red_add_v4(float* p, float x, float y, float z, float w) {
    asm volatile("red.global.add.v4.f32 [%0], {%1,%2,%3,%4};"
                 :: "l"(p), "f"(x), "f"(y), "f"(z), "f"(w) : "memory");
}

// ---------------------------------------------------------------------------
// 1) PREP: zero accumulators | att table | disen  (block-split persistent)
//    att: warp per entity, lane per relation, rel row REGISTER-resident,
//    4 independent accumulator chains (no smem, no LDS in the hot loop).
// ---------------------------------------------------------------------------
__global__ void __launch_bounds__(256)
prep_kernel(const float* __restrict__ ent,
            const float* __restrict__ relw,
            const float* __restrict__ datt,
            const float* __restrict__ weight,
            float4* __restrict__ out) {
    int b = blockIdx.x;

    if (b < ZERO_BLOCKS) {
        // ---- zero outputs + counts ----
        const int total4 = (N_ENTITIES + N_USERS) * CHANNEL / 4;
        int i0     = b * 256 + threadIdx.x;
        int stride = ZERO_BLOCKS * 256;
        for (int i = i0; i < total4; i += stride)
            out[i] = make_float4(0.f, 0.f, 0.f, 0.f);
        for (int i = i0; i < N_ENTITIES; i += stride)
            g_cnt[i] = 0.0f;

    } else if (b < ZERO_BLOCKS + ATT_BLOCKS) {
        // ---- attention table ----
        int lane = threadIdx.x & 31;

        // lane r caches rel[r][:] in registers (zeros for lane 31)
        float4 rrel[16];
        if (lane < N_REL_USED) {
            const float4* rw = (const float4*)&relw[lane * CHANNEL];
            #pragma unroll
            for (int i = 0; i < 16; i++) rrel[i] = __ldg(&rw[i]);
        } else {
            #pragma unroll
            for (int i = 0; i < 16; i++) rrel[i] = make_float4(0.f, 0.f, 0.f, 0.f);
        }

        int warp0  = ((b - ZERO_BLOCKS) * 256 + threadIdx.x) >> 5;
        int nwarps = (ATT_BLOCKS * 256) >> 5;

        for (int h = warp0; h < N_ENTITIES; h += nwarps) {
            const float4* row = (const float4*)&ent[(size_t)h * CHANNEL];
            float d0 = 0.f, d1 = 0.f, d2 = 0.f, d3 = 0.f;
            #pragma unroll
            for (int i = 0; i < 16; i++) {
                float4 a = __ldg(&row[i]);       // uniform -> 1-line broadcast
                d0 += a.x * rrel[i].x;
                d1 += a.y * rrel[i].y;
                d2 += a.z * rrel[i].z;
                d3 += a.w * rrel[i].w;
            }
            float d = (d0 + d1) + (d2 + d3);
            if (lane < N_REL_USED)
                g_att[h * N_REL_USED + lane] = 1.0f / (1.0f + __expf(-d));
        }

    } else {
        // ---- disen_weight = softmax(disen_weight_att, -1) @ weight ----
        int c = threadIdx.x;
        if (c >= CHANNEL) return;
        #pragma unroll
        for (int f = 0; f < N_FACTORS; f++) {
            float a[N_META];
            float m = -1e30f;
            #pragma unroll
            for (int j = 0; j < N_META; j++) { a[j] = datt[f * N_META + j]; m = fmaxf(m, a[j]); }
            float s = 0.0f;
            #pragma unroll
            for (int j = 0; j < N_META; j++) { a[j] = __expf(a[j] - m); s += a[j]; }
            float inv = 1.0f / s;
            float acc = 0.0f;
            #pragma unroll
            for (int j = 0; j < N_META; j++) acc += a[j] * inv * weight[j * CHANNEL + c];
            g_disen[f * CHANNEL + c] = acc;
        }
    }
}

// ---------------------------------------------------------------------------
// 2) PERSISTENT fused scatter: block-split edge / spmm, grid-stride loops,
//    half-warp (16 lanes x float4) per item.  At the LTS atomic roofline.
// ---------------------------------------------------------------------------
__global__ void __launch_bounds__(256)
fused_scatter_kernel(const float* __restrict__ ent,
                     const int*   __restrict__ head,
                     const int*   __restrict__ tail,
                     const int*   __restrict__ etype,
                     const int*   __restrict__ mrow,
                     const int*   __restrict__ mcol,
                     const float* __restrict__ mval,
                     const float* __restrict__ relw,
                     float* __restrict__ out_ent,
                     float* __restrict__ out_user) {
    int li = threadIdx.x & 15;

    if (blockIdx.x < EDGE_BLOCKS) {
        // ---------------- edge path ----------------
        __shared__ float s_rel[N_REL_USED * CHANNEL];
        for (int i = threadIdx.x; i < N_REL_USED * CHANNEL; i += blockDim.x)
            s_rel[i] = relw[i];
        __syncthreads();

        int hw     = blockIdx.x * HW_PER_BLOCK + (threadIdx.x >> 4);
        int stride = EDGE_BLOCKS * HW_PER_BLOCK;

        for (int e = hw; e < N_EDGES; e += stride) {
            int h  = __ldg(&head[e]);
            int t  = __ldg(&tail[e]);
            int ri = __ldg(&etype[e]) - 1;

            float  att = __ldg(&g_att[h * N_REL_USED + ri]);
            float4 rel = *(const float4*)&s_rel[ri * CHANNEL + li * 4];
            float4 et  = __ldg((const float4*)&ent[(size_t)t * CHANNEL + li * 4]);

            red_add_v4(&out_ent[(size_t)h * CHANNEL + li * 4],
                       att * et.x * rel.x, att * et.y * rel.y,
                       att * et.z * rel.z, att * et.w * rel.w);
            if (li == 0)
                asm volatile("red.global.add.f32 [%0], %1;"
                             :: "l"(&g_cnt[h]), "f"(1.0f) : "memory");
        }
    } else {
        // ---------------- spmm path ----------------
        int hw     = (blockIdx.x - EDGE_BLOCKS) * HW_PER_BLOCK + (threadIdx.x >> 4);
        int stride = SPMM_BLOCKS * HW_PER_BLOCK;

        for (int i = hw; i < NNZ_CNT; i += stride) {
            int   r = __ldg(&mrow[i]);
            int   c = __ldg(&mcol[i]);
            float v = __ldg(&mval[i]);
            float4 e4 = __ldg((const float4*)&ent[(size_t)c * CHANNEL + li * 4]);
            red_add_v4(&out_user[(size_t)r * CHANNEL + li * 4],
                       v * e4.x, v * e4.y, v * e4.z, v * e4.w);
        }
    }
}

// ---------------------------------------------------------------------------
// 3) FINAL: entity mean-divide | user softmax-blend  (block-split)
// ---------------------------------------------------------------------------
__global__ void __launch_bounds__(256)
final_kernel(const float* __restrict__ user_emb,
             const float* __restrict__ latent,
             float4* __restrict__ out_ent4,
             float* __restrict__ out_user) {
    int b = blockIdx.x;

    if (b < ENTF_BLOCKS) {
        // ---- entity scatter_mean divide ----
        int i = b * 256 + threadIdx.x;
        if (i >= N_ENTITIES * (CHANNEL / 4)) return;
        float inv = 1.0f / fmaxf(g_cnt[i >> 4], 1.0f);
        float4 v = out_ent4[i];
        v.x *= inv; v.y *= inv; v.z *= inv; v.w *= inv;
        out_ent4[i] = v;

    } else {
        // ---- user: score softmax + disen blend, warp per user ----
        __shared__ float s_lat[N_FACTORS * CHANNEL];
        __shared__ float s_dis[N_FACTORS * CHANNEL];
        for (int i = threadIdx.x; i < N_FACTORS * CHANNEL; i += blockDim.x) {
            s_lat[i] = latent[i];
            s_dis[i] = g_disen[i];
        }
        __syncthreads();

        int u    = (b - ENTF_BLOCKS) * 8 + (threadIdx.x >> 5);
        int lane = threadIdx.x & 31;
        if (u >= N_USERS) return;

        float2 ue = *(const float2*)&user_emb[(size_t)u * CHANNEL + lane * 2];

        float s[N_FACTORS];
        #pragma unroll
        for (int f = 0; f < N_FACTORS; f++) {
            float p = ue.x * s_lat[f * CHANNEL + lane * 2]
                    + ue.y * s_lat[f * CHANNEL + lane * 2 + 1];
            #pragma unroll
            for (int o = 16; o > 0; o >>= 1) p += __shfl_xor_sync(0xFFFFFFFFu, p, o);
            s[f] = p;
        }
        float m = fmaxf(fmaxf(s[0], s[1]), fmaxf(s[2], s[3]));
        float sum = 0.0f;
        #pragma unroll
        for (int f = 0; f < N_FACTORS; f++) { s[f] = __expf(s[f] - m); sum += s[f]; }
        float inv = 1.0f / sum;

        float cx = 0.0f, cy = 0.0f;
        #pragma unroll
        for (int f = 0; f < N_FACTORS; f++) {
            float sc = s[f] * inv;
            cx += sc * s_dis[f * CHANNEL + lane * 2];
            cy += sc * s_dis[f * CHANNEL + lane * 2 + 1];
        }

        float2* p = (float2*)&out_user[(size_t)u * CHANNEL + lane * 2];
        float2 a = *p;
        a.x = a.x * (1.0f + cx);
        a.y = a.y * (1.0f + cy);
        *p = a;
    }
}

// ---------------------------------------------------------------------------
extern "C" void kernel_launch(void* const* d_in, const int* in_sizes, int n_in,
                              void* d_out, int out_size)
{
    const float* entity_emb = (const float*)d_in[0];
    const float* user_emb   = (const float*)d_in[1];
    const float* latent_emb = (const float*)d_in[2];
    const int*   head       = (const int*)d_in[3];
    const int*   tail       = (const int*)d_in[4];
    const int*   edge_type  = (const int*)d_in[5];
    const int*   mat_row    = (const int*)d_in[6];
    const int*   mat_col    = (const int*)d_in[7];
    const float* mat_val    = (const float*)d_in[8];
    const float* rel_w      = (const float*)d_in[9];
    const float* weight     = (const float*)d_in[10];
    const float* disen_att  = (const float*)d_in[11];

    float* out      = (float*)d_out;
    float* out_ent  = out;                                 // (N_ENTITIES, 64)
    float* out_user = out + (size_t)N_ENTITIES * CHANNEL;  // (N_USERS, 64)

    prep_kernel<<<PREP_BLOCKS, 256>>>(entity_emb, rel_w, disen_att, weight,
                                      (float4*)out);

    fused_scatter_kernel<<<TOTAL_BLOCKS, 256>>>(entity_emb, head, tail, edge_type,
                                                mat_row, mat_col, mat_val, rel_w,
                                                out_ent, out_user);

    final_kernel<<<FINAL_BLOCKS, 256>>>(user_emb, latent_emb,
                                        (float4*)out_ent, out_user);
}

// round 9
// speedup vs baseline: 1.1346x; 1.1346x over previous
#include <cuda_runtime.h>
#include <cstdint>

#define N_ENTITIES 100000
#define N_USERS    50000
#define N_FACTORS  4
#define N_RELATIONS 32
#define N_REL_USED 31
#define N_META     8
#define CHANNEL    64
#define N_EDGES    1600000
#define NNZ_CNT    1000000

// persistent-grid split for the fused scatter
#define EDGE_BLOCKS 740
#define SPMM_BLOCKS 444
#define TOTAL_BLOCKS (EDGE_BLOCKS + SPMM_BLOCKS)
#define HW_PER_BLOCK 16                     // 256 threads / 16 lanes

// prep kernel split
#define ZERO_BLOCKS 296
#define ATT_BLOCKS  888
#define PREP_BLOCKS (ZERO_BLOCKS + ATT_BLOCKS + 1)   // +1 block for disen

#define TILE_E 64                            // entities staged per block tile
#define ATT_TILES ((N_ENTITIES + TILE_E - 1) / TILE_E)   // 1563

// final kernel split
#define ENTF_BLOCKS 6250     // entity mean: 1.6M float4 / 256
#define USERF_BLOCKS 6250    // users: 50000 / 8 warps
#define FINAL_BLOCKS (ENTF_BLOCKS + USERF_BLOCKS)

// ------------------------- device-global scratch ---------------------------
__device__ float g_cnt[N_ENTITIES];
__device__ float g_disen[N_FACTORS * CHANNEL];
__device__ float g_att[N_ENTITIES * N_REL_USED];   // sigmoid(ent[h] . rel[r])

__device__ __forceinline__ void red_add_v4(float* p, float x, float y, float z, float w) {
    asm volatile("red.global.add.v4.f32 [%0], {%1,%2,%3,%4};"
                 :: "l"(p), "f"(x), "f"(y), "f"(z), "f"(w) : "memory");
}

// ---------------------------------------------------------------------------
// 1) PREP: zero accumulators | att table | disen  (block-split persistent)
//    att: 64-entity smem tile staging, warp computes 8 entities,
//    lane-per-relation with REGISTER-resident rel rows, broadcast LDS reads.
// ---------------------------------------------------------------------------
__global__ void __launch_bounds__(256)
prep_kernel(const float* __restrict__ ent,
            const float* __restrict__ relw,
            const float* __restrict__ datt,
            const float* __restrict__ weight,
            float4* __restrict__ out) {
    int b = blockIdx.x;

    if (b < ZERO_BLOCKS) {
        // ---- zero outputs + counts ----
        const int total4 = (N_ENTITIES + N_USERS) * CHANNEL / 4;
        int i0     = b * 256 + threadIdx.x;
        int stride = ZERO_BLOCKS * 256;
        for (int i = i0; i < total4; i += stride)
            out[i] = make_float4(0.f, 0.f, 0.f, 0.f);
        for (int i = i0; i < N_ENTITIES; i += stride)
            g_cnt[i] = 0.0f;

    } else if (b < ZERO_BLOCKS + ATT_BLOCKS) {
        // ---- attention table ----
        __shared__ float s_ent[TILE_E * CHANNEL];     // 16 KB tile
        int lane = threadIdx.x & 31;
        int wid  = threadIdx.x >> 5;

        // lane r caches rel[r][:] in registers (zeros for lane 31)
        float4 rrel[16];
        if (lane < N_REL_USED) {
            const float4* rw = (const float4*)&relw[lane * CHANNEL];
            #pragma unroll
            for (int i = 0; i < 16; i++) rrel[i] = __ldg(&rw[i]);
        } else {
            #pragma unroll
            for (int i = 0; i < 16; i++) rrel[i] = make_float4(0.f, 0.f, 0.f, 0.f);
        }

        int tile0 = b - ZERO_BLOCKS;
        for (int tile = tile0; tile < ATT_TILES; tile += ATT_BLOCKS) {
            int base = tile * TILE_E;
            int cnt  = min(TILE_E, N_ENTITIES - base);

            __syncthreads();                          // protect prior tile reads
            const float4* src = (const float4*)&ent[(size_t)base * CHANNEL];
            for (int i = threadIdx.x; i < cnt * (CHANNEL / 4); i += 256)
                ((float4*)s_ent)[i] = __ldg(&src[i]); // coalesced stream
            __syncthreads();

            for (int k = wid; k < cnt; k += 8) {
                const float4* row = (const float4*)&s_ent[k * CHANNEL];
                float d0 = 0.f, d1 = 0.f, d2 = 0.f, d3 = 0.f;
                #pragma unroll
                for (int i = 0; i < 16; i++) {
                    float4 a = row[i];                // broadcast LDS.128 (N=1)
                    d0 += a.x * rrel[i].x;
                    d1 += a.y * rrel[i].y;
                    d2 += a.z * rrel[i].z;
                    d3 += a.w * rrel[i].w;
                }
                float d = (d0 + d1) + (d2 + d3);
                if (lane < N_REL_USED)
                    g_att[(size_t)(base + k) * N_REL_USED + lane] =
                        1.0f / (1.0f + __expf(-d));
            }
        }

    } else {
        // ---- disen_weight = softmax(disen_weight_att, -1) @ weight ----
        int c = threadIdx.x;
        if (c >= CHANNEL) return;
        #pragma unroll
        for (int f = 0; f < N_FACTORS; f++) {
            float a[N_META];
            float m = -1e30f;
            #pragma unroll
            for (int j = 0; j < N_META; j++) { a[j] = datt[f * N_META + j]; m = fmaxf(m, a[j]); }
            float s = 0.0f;
            #pragma unroll
            for (int j = 0; j < N_META; j++) { a[j] = __expf(a[j] - m); s += a[j]; }
            float inv = 1.0f / s;
            float acc = 0.0f;
            #pragma unroll
            for (int j = 0; j < N_META; j++) acc += a[j] * inv * weight[j * CHANNEL + c];
            g_disen[f * CHANNEL + c] = acc;
        }
    }
}

// ---------------------------------------------------------------------------
// 2) PERSISTENT fused scatter: block-split edge / spmm, grid-stride loops,
//    half-warp (16 lanes x float4) per item.  At the LTS atomic roofline.
// ---------------------------------------------------------------------------
__global__ void __launch_bounds__(256)
fused_scatter_kernel(const float* __restrict__ ent,
                     const int*   __restrict__ head,
                     const int*   __restrict__ tail,
                     const int*   __restrict__ etype,
                     const int*   __restrict__ mrow,
                     const int*   __restrict__ mcol,
                     const float* __restrict__ mval,
                     const float* __restrict__ relw,
                     float* __restrict__ out_ent,
                     float* __restrict__ out_user) {
    int li = threadIdx.x & 15;

    if (blockIdx.x < EDGE_BLOCKS) {
        // ---------------- edge path ----------------
        __shared__ float s_rel[N_REL_USED * CHANNEL];
        for (int i = threadIdx.x; i < N_REL_USED * CHANNEL; i += blockDim.x)
            s_rel[i] = relw[i];
        __syncthreads();

        int hw     = blockIdx.x * HW_PER_BLOCK + (threadIdx.x >> 4);
        int stride = EDGE_BLOCKS * HW_PER_BLOCK;

        for (int e = hw; e < N_EDGES; e += stride) {
            int h  = __ldg(&head[e]);
            int t  = __ldg(&tail[e]);
            int ri = __ldg(&etype[e]) - 1;

            float  att = __ldg(&g_att[h * N_REL_USED + ri]);
            float4 rel = *(const float4*)&s_rel[ri * CHANNEL + li * 4];
            float4 et  = __ldg((const float4*)&ent[(size_t)t * CHANNEL + li * 4]);

            red_add_v4(&out_ent[(size_t)h * CHANNEL + li * 4],
                       att * et.x * rel.x, att * et.y * rel.y,
                       att * et.z * rel.z, att * et.w * rel.w);
            if (li == 0)
                asm volatile("red.global.add.f32 [%0], %1;"
                             :: "l"(&g_cnt[h]), "f"(1.0f) : "memory");
        }
    } else {
        // ---------------- spmm path ----------------
        int hw     = (blockIdx.x - EDGE_BLOCKS) * HW_PER_BLOCK + (threadIdx.x >> 4);
        int stride = SPMM_BLOCKS * HW_PER_BLOCK;

        for (int i = hw; i < NNZ_CNT; i += stride) {
            int   r = __ldg(&mrow[i]);
            int   c = __ldg(&mcol[i]);
            float v = __ldg(&mval[i]);
            float4 e4 = __ldg((const float4*)&ent[(size_t)c * CHANNEL + li * 4]);
            red_add_v4(&out_user[(size_t)r * CHANNEL + li * 4],
                       v * e4.x, v * e4.y, v * e4.z, v * e4.w);
        }
    }
}

// ---------------------------------------------------------------------------
// 3) FINAL: entity mean-divide | user softmax-blend  (block-split)
// ---------------------------------------------------------------------------
__global__ void __launch_bounds__(256)
final_kernel(const float* __restrict__ user_emb,
             const float* __restrict__ latent,
             float4* __restrict__ out_ent4,
             float* __restrict__ out_user) {
    int b = blockIdx.x;

    if (b < ENTF_BLOCKS) {
        // ---- entity scatter_mean divide ----
        int i = b * 256 + threadIdx.x;
        if (i >= N_ENTITIES * (CHANNEL / 4)) return;
        float inv = 1.0f / fmaxf(g_cnt[i >> 4], 1.0f);
        float4 v = out_ent4[i];
        v.x *= inv; v.y *= inv; v.z *= inv; v.w *= inv;
        out_ent4[i] = v;

    } else {
        // ---- user: score softmax + disen blend, warp per user ----
        __shared__ float s_lat[N_FACTORS * CHANNEL];
        __shared__ float s_dis[N_FACTORS * CHANNEL];
        for (int i = threadIdx.x; i < N_FACTORS * CHANNEL; i += blockDim.x) {
            s_lat[i] = latent[i];
            s_dis[i] = g_disen[i];
        }
        __syncthreads();

        int u    = (b - ENTF_BLOCKS) * 8 + (threadIdx.x >> 5);
        int lane = threadIdx.x & 31;
        if (u >= N_USERS) return;

        float2 ue = *(const float2*)&user_emb[(size_t)u * CHANNEL + lane * 2];

        float s[N_FACTORS];
        #pragma unroll
        for (int f = 0; f < N_FACTORS; f++) {
            float p = ue.x * s_lat[f * CHANNEL + lane * 2]
                    + ue.y * s_lat[f * CHANNEL + lane * 2 + 1];
            #pragma unroll
            for (int o = 16; o > 0; o >>= 1) p += __shfl_xor_sync(0xFFFFFFFFu, p, o);
            s[f] = p;
        }
        float m = fmaxf(fmaxf(s[0], s[1]), fmaxf(s[2], s[3]));
        float sum = 0.0f;
        #pragma unroll
        for (int f = 0; f < N_FACTORS; f++) { s[f] = __expf(s[f] - m); sum += s[f]; }
        float inv = 1.0f / sum;

        float cx = 0.0f, cy = 0.0f;
        #pragma unroll
        for (int f = 0; f < N_FACTORS; f++) {
            float sc = s[f] * inv;
            cx += sc * s_dis[f * CHANNEL + lane * 2];
            cy += sc * s_dis[f * CHANNEL + lane * 2 + 1];
        }

        float2* p = (float2*)&out_user[(size_t)u * CHANNEL + lane * 2];
        float2 a = *p;
        a.x = a.x * (1.0f + cx);
        a.y = a.y * (1.0f + cy);
        *p = a;
    }
}

// ---------------------------------------------------------------------------
extern "C" void kernel_launch(void* const* d_in, const int* in_sizes, int n_in,
                              void* d_out, int out_size)
{
    const float* entity_emb = (const float*)d_in[0];
    const float* user_emb   = (const float*)d_in[1];
    const float* latent_emb = (const float*)d_in[2];
    const int*   head       = (const int*)d_in[3];
    const int*   tail       = (const int*)d_in[4];
    const int*   edge_type  = (const int*)d_in[5];
    const int*   mat_row    = (const int*)d_in[6];
    const int*   mat_col    = (const int*)d_in[7];
    const float* mat_val    = (const float*)d_in[8];
    const float* rel_w      = (const float*)d_in[9];
    const float* weight     = (const float*)d_in[10];
    const float* disen_att  = (const float*)d_in[11];

    float* out      = (float*)d_out;
    float* out_ent  = out;                                 // (N_ENTITIES, 64)
    float* out_user = out + (size_t)N_ENTITIES * CHANNEL;  // (N_USERS, 64)

    prep_kernel<<<PREP_BLOCKS, 256>>>(entity_emb, rel_w, disen_att, weight,
                                      (float4*)out);

    fused_scatter_kernel<<<TOTAL_BLOCKS, 256>>>(entity_emb, head, tail, edge_type,
                                                mat_row, mat_col, mat_val, rel_w,
                                                out_ent, out_user);

    final_kernel<<<FINAL_BLOCKS, 256>>>(user_emb, latent_emb,
                                        (float4*)out_ent, out_user);
}